// round 3
// baseline (speedup 1.0000x reference)
#include <cuda_runtime.h>
#include <cuda_bf16.h>
#include <math_constants.h>

// ---------------------------------------------------------------------------
// GroupPooling: per-agent MLP score -> segment softmax over teams ->
// attention-weighted team pooling -> output projection + relu.
// Shapes (fixed dataset): agents=400000, hidden=256, h2=128, teams=100000.
// ---------------------------------------------------------------------------

#define HIDDEN   256
#define H2       128
#define MAX_AGENTS 400000
#define MAX_TEAMS  100000

// ---- device scratch (static globals; no runtime allocation) ----------------
__device__ float g_scores[MAX_AGENTS];             // scores, then exp values
__device__ int   g_counts[MAX_TEAMS];
__device__ int   g_offs[MAX_TEAMS + 1];
__device__ int   g_order[MAX_AGENTS];
__device__ int   g_idx64;                          // 1 if team_idx is int64
__device__ float g_team_pre[(size_t)MAX_TEAMS * HIDDEN];  // 102.4 MB

// ---- f32x2 packed helpers ---------------------------------------------------
__device__ __forceinline__ unsigned long long pk2(float lo, float hi) {
    unsigned long long r;
    asm("mov.b64 %0, {%1, %2};" : "=l"(r) : "f"(lo), "f"(hi));
    return r;
}
__device__ __forceinline__ float2 upk2(unsigned long long v) {
    float2 r;
    asm("mov.b64 {%0, %1}, %2;" : "=f"(r.x), "=f"(r.y) : "l"(v));
    return r;
}
#define FMA2(acc, a, b) \
    asm("fma.rn.f32x2 %0, %1, %2, %0;" : "+l"(acc) : "l"(a), "l"(b))

// ---------------------------------------------------------------------------
// dtype detection: interpret first K entries as int64. For a real int64
// buffer every value is in [0, n_teams). For an int32 buffer misread as
// int64, values pack two random indices -> almost surely >= 2^32.
// Single block, deterministic.
// ---------------------------------------------------------------------------
__global__ void k_detect(const void* __restrict__ team_idx, int n_agents,
                         int n_teams) {
    __shared__ int ok_s;
    if (threadIdx.x == 0) ok_s = 1;
    __syncthreads();
    int K = n_agents < 1024 ? n_agents : 1024;
    // reading K int64s = 8K bytes; an int32 buffer holds 4*n_agents bytes,
    // and 8*1024 <= 4*400000, so this never reads out of bounds.
    const long long* p = (const long long*)team_idx;
    for (int i = threadIdx.x; i < K; i += blockDim.x) {
        long long v = p[i];
        if (v < 0 || v >= (long long)n_teams) ok_s = 0;
    }
    __syncthreads();
    if (threadIdx.x == 0) g_idx64 = ok_s;
}

__device__ __forceinline__ int load_team(const void* team_idx, int a,
                                         int n_teams) {
    int t;
    if (g_idx64) t = (int)((const long long*)team_idx)[a];
    else         t = ((const int*)team_idx)[a];
    // clamp: never let a surprise dtype escalate to an illegal access
    if (t < 0) t = 0;
    if (t >= n_teams) t = n_teams - 1;
    return t;
}

// ---------------------------------------------------------------------------
// CSR build
// ---------------------------------------------------------------------------
__global__ void k_zero_counts(int n_teams) {
    int i = blockIdx.x * blockDim.x + threadIdx.x;
    if (i < n_teams) g_counts[i] = 0;
}

__global__ void k_count(const void* __restrict__ team_idx, int n_agents,
                        int n_teams) {
    int a = blockIdx.x * blockDim.x + threadIdx.x;
    if (a < n_agents) {
        int t = load_team(team_idx, a, n_teams);
        atomicAdd(&g_counts[t], 1);
    }
}

// single-block exclusive scan of g_counts -> g_offs
__global__ void k_scan(int n_teams) {
    __shared__ int s[1024];
    __shared__ int carry_s;
    int tid = threadIdx.x;
    if (tid == 0) carry_s = 0;
    __syncthreads();
    for (int base = 0; base < n_teams; base += 1024) {
        int v = (base + tid < n_teams) ? g_counts[base + tid] : 0;
        s[tid] = v;
        __syncthreads();
        for (int off = 1; off < 1024; off <<= 1) {
            int t2 = (tid >= off) ? s[tid - off] : 0;
            __syncthreads();
            s[tid] += t2;
            __syncthreads();
        }
        if (base + tid < n_teams) g_offs[base + tid] = carry_s + s[tid] - v;
        __syncthreads();
        if (tid == 0) carry_s += s[1023];
        __syncthreads();
    }
}

__global__ void k_fill(const void* __restrict__ team_idx, int n_agents,
                       int n_teams) {
    int a = blockIdx.x * blockDim.x + threadIdx.x;
    if (a < n_agents) {
        int t = load_team(team_idx, a, n_teams);
        int pos = atomicAdd(&g_offs[t], 1);   // g_offs[t] becomes END of team t
        g_order[pos] = a;
    }
}

// ---------------------------------------------------------------------------
// k_scores: scores[a] = W2 . tanh(W1^T x_a + b1) + b2
// Block: 256 threads = 8 warps. Each warp: 8 agents x 128 cols.
// Each lane: 4 cols (f32x2 pairs) x 8 agents. W1 resident in smem (128 KB),
// x rows staged in smem (64 KB). Grid-stride over agents in chunks of 64.
// ---------------------------------------------------------------------------
__global__ void k_scores(const float* __restrict__ agent_h,
                         const float* __restrict__ W1,
                         const float* __restrict__ b1,
                         const float* __restrict__ W2,
                         const float* __restrict__ b2,
                         int n_agents) {
    extern __shared__ float smem[];
    float* W1s = smem;                 // 256*128 floats
    float* xs  = smem + HIDDEN * H2;   // 64*256 floats

    const int tid    = threadIdx.x;
    const int warpId = tid >> 5;
    const int lane   = tid & 31;

    // stage W1 into smem
    {
        const float4* src = (const float4*)W1;
        float4* dst = (float4*)W1s;
        for (int k = tid; k < (HIDDEN * H2) / 4; k += 256) dst[k] = src[k];
    }

    const float4 b1v = ((const float4*)b1)[lane];
    const float4 w2v = ((const float4*)W2)[lane];
    const float  b2s = __ldg(b2);

    for (int base = blockIdx.x * 64; base < n_agents; base += gridDim.x * 64) {
        // stage 64 agent rows (zero-pad tail)
        {
            float4* xs4 = (float4*)xs;
            const float4* g4 = (const float4*)agent_h;
            for (int k = 0; k < 16; k++) {
                int v = tid + k * 256;           // 0..4095
                int row = v >> 6;                // 64 float4 per row
                int c4  = v & 63;
                int r   = base + row;
                xs4[v] = (r < n_agents) ? g4[(size_t)r * 64 + c4]
                                        : make_float4(0.f, 0.f, 0.f, 0.f);
            }
        }
        __syncthreads();

        unsigned long long accA[8], accB[8];
#pragma unroll
        for (int a = 0; a < 8; a++) { accA[a] = 0ull; accB[a] = 0ull; }

        const float* xr = xs + warpId * 8 * HIDDEN;
        const int colBase = 4 * lane;

#pragma unroll 2
        for (int i = 0; i < HIDDEN; i += 4) {
            const float* wr = &W1s[i * H2 + colBase];
            unsigned long long wA0 = *(const unsigned long long*)(wr);
            unsigned long long wB0 = *(const unsigned long long*)(wr + 2);
            unsigned long long wA1 = *(const unsigned long long*)(wr + H2);
            unsigned long long wB1 = *(const unsigned long long*)(wr + H2 + 2);
            unsigned long long wA2 = *(const unsigned long long*)(wr + 2 * H2);
            unsigned long long wB2 = *(const unsigned long long*)(wr + 2 * H2 + 2);
            unsigned long long wA3 = *(const unsigned long long*)(wr + 3 * H2);
            unsigned long long wB3 = *(const unsigned long long*)(wr + 3 * H2 + 2);
#pragma unroll
            for (int a = 0; a < 8; a++) {
                float4 x4 = *(const float4*)(xr + a * HIDDEN + i);
                unsigned long long x0 = pk2(x4.x, x4.x);
                unsigned long long x1 = pk2(x4.y, x4.y);
                unsigned long long x2 = pk2(x4.z, x4.z);
                unsigned long long x3 = pk2(x4.w, x4.w);
                FMA2(accA[a], x0, wA0); FMA2(accB[a], x0, wB0);
                FMA2(accA[a], x1, wA1); FMA2(accB[a], x1, wB1);
                FMA2(accA[a], x2, wA2); FMA2(accB[a], x2, wB2);
                FMA2(accA[a], x3, wA3); FMA2(accB[a], x3, wB3);
            }
        }

#pragma unroll
        for (int a = 0; a < 8; a++) {
            float2 hA = upk2(accA[a]);
            float2 hB = upk2(accB[a]);
            float h0 = tanhf(hA.x + b1v.x);
            float h1 = tanhf(hA.y + b1v.y);
            float h2 = tanhf(hB.x + b1v.z);
            float h3 = tanhf(hB.y + b1v.w);
            float sp = h0 * w2v.x + h1 * w2v.y + h2 * w2v.z + h3 * w2v.w;
#pragma unroll
            for (int o = 16; o > 0; o >>= 1)
                sp += __shfl_xor_sync(0xFFFFFFFFu, sp, o);
            int row = base + warpId * 8 + a;
            if (lane == 0 && row < n_agents) g_scores[row] = sp + b2s;
        }
        __syncthreads();
    }
}

// ---------------------------------------------------------------------------
// k_team: one warp per team. Segment softmax over its agents + weighted pool.
// ---------------------------------------------------------------------------
__global__ void k_team(const float* __restrict__ agent_h,
                       float* __restrict__ out_attn,
                       int n_teams) {
    int t = blockIdx.x * 8 + (threadIdx.x >> 5);
    int lane = threadIdx.x & 31;
    if (t >= n_teams) return;

    int end   = g_offs[t];
    int cnt   = g_counts[t];
    int start = end - cnt;

    // per-team max
    float m = -CUDART_INF_F;
    for (int b = 0; b < cnt; b += 32) {
        int i = b + lane;
        float s = (i < cnt) ? g_scores[g_order[start + i]] : -CUDART_INF_F;
        m = fmaxf(m, s);
    }
#pragma unroll
    for (int o = 16; o > 0; o >>= 1)
        m = fmaxf(m, __shfl_xor_sync(0xFFFFFFFFu, m, o));

    // exp + sum (store e back into g_scores)
    float esum = 0.f;
    for (int b = 0; b < cnt; b += 32) {
        int i = b + lane;
        if (i < cnt) {
            int a = g_order[start + i];
            float e = expf(g_scores[a] - m);
            g_scores[a] = e;
            esum += e;
        }
    }
#pragma unroll
    for (int o = 16; o > 0; o >>= 1)
        esum += __shfl_xor_sync(0xFFFFFFFFu, esum, o);
    __syncwarp();

    float inv = (cnt > 0) ? (1.f / esum) : 0.f;

    float4 acc0 = make_float4(0.f, 0.f, 0.f, 0.f);
    float4 acc1 = make_float4(0.f, 0.f, 0.f, 0.f);
    for (int mI = 0; mI < cnt; mI++) {
        int a = g_order[start + mI];
        float wgt = g_scores[a] * inv;
        if (lane == 0) out_attn[a] = wgt;
        const float4* row = (const float4*)(agent_h + (size_t)a * HIDDEN);
        float4 x0 = row[lane];
        float4 x1 = row[32 + lane];
        acc0.x += wgt * x0.x; acc0.y += wgt * x0.y;
        acc0.z += wgt * x0.z; acc0.w += wgt * x0.w;
        acc1.x += wgt * x1.x; acc1.y += wgt * x1.y;
        acc1.z += wgt * x1.z; acc1.w += wgt * x1.w;
    }
    float4* dst = (float4*)(g_team_pre + (size_t)t * HIDDEN);
    dst[lane]      = acc0;
    dst[32 + lane] = acc1;
}

// ---------------------------------------------------------------------------
// k_out: out = relu(team_pre @ Wo + bo). gridDim.y selects the column half
// (128 cols, 128 KB of Wo in smem). Same register blocking as k_scores.
// ---------------------------------------------------------------------------
__global__ void k_out(const float* __restrict__ Wo,
                      const float* __restrict__ bo,
                      float* __restrict__ out_team,
                      int n_teams) {
    extern __shared__ float smem[];
    float* Wos = smem;                 // 256*128 floats (half of Wo)
    float* xs  = smem + HIDDEN * H2;   // 64*256 floats

    const int tid    = threadIdx.x;
    const int warpId = tid >> 5;
    const int lane   = tid & 31;
    const int H = blockIdx.y;          // 0 or 1

    // stage Wo[:, H*128 .. H*128+127] into smem
    {
        const float4* src = (const float4*)Wo;
        float4* dst = (float4*)Wos;
        for (int v = tid; v < 8192; v += 256) {
            int row = v >> 5;          // 32 float4 per smem row
            int c   = v & 31;
            dst[v] = src[row * 64 + H * 32 + c];
        }
    }

    const float4 bov = ((const float4*)bo)[H * 32 + lane];

    for (int base = blockIdx.x * 64; base < n_teams; base += gridDim.x * 64) {
        {
            float4* xs4 = (float4*)xs;
            const float4* g4 = (const float4*)g_team_pre;
            for (int k = 0; k < 16; k++) {
                int v = tid + k * 256;
                int row = v >> 6;
                int c4  = v & 63;
                int r   = base + row;
                xs4[v] = (r < n_teams) ? g4[(size_t)r * 64 + c4]
                                       : make_float4(0.f, 0.f, 0.f, 0.f);
            }
        }
        __syncthreads();

        unsigned long long accA[8], accB[8];
#pragma unroll
        for (int a = 0; a < 8; a++) { accA[a] = 0ull; accB[a] = 0ull; }

        const float* xr = xs + warpId * 8 * HIDDEN;
        const int colBase = 4 * lane;

#pragma unroll 2
        for (int i = 0; i < HIDDEN; i += 4) {
            const float* wr = &Wos[i * H2 + colBase];
            unsigned long long wA0 = *(const unsigned long long*)(wr);
            unsigned long long wB0 = *(const unsigned long long*)(wr + 2);
            unsigned long long wA1 = *(const unsigned long long*)(wr + H2);
            unsigned long long wB1 = *(const unsigned long long*)(wr + H2 + 2);
            unsigned long long wA2 = *(const unsigned long long*)(wr + 2 * H2);
            unsigned long long wB2 = *(const unsigned long long*)(wr + 2 * H2 + 2);
            unsigned long long wA3 = *(const unsigned long long*)(wr + 3 * H2);
            unsigned long long wB3 = *(const unsigned long long*)(wr + 3 * H2 + 2);
#pragma unroll
            for (int a = 0; a < 8; a++) {
                float4 x4 = *(const float4*)(xr + a * HIDDEN + i);
                unsigned long long x0 = pk2(x4.x, x4.x);
                unsigned long long x1 = pk2(x4.y, x4.y);
                unsigned long long x2 = pk2(x4.z, x4.z);
                unsigned long long x3 = pk2(x4.w, x4.w);
                FMA2(accA[a], x0, wA0); FMA2(accB[a], x0, wB0);
                FMA2(accA[a], x1, wA1); FMA2(accB[a], x1, wB1);
                FMA2(accA[a], x2, wA2); FMA2(accB[a], x2, wB2);
                FMA2(accA[a], x3, wA3); FMA2(accB[a], x3, wB3);
            }
        }

#pragma unroll
        for (int a = 0; a < 8; a++) {
            int row = base + warpId * 8 + a;
            if (row < n_teams) {
                float2 oA = upk2(accA[a]);
                float2 oB = upk2(accB[a]);
                float4 o;
                o.x = fmaxf(oA.x + bov.x, 0.f);
                o.y = fmaxf(oA.y + bov.y, 0.f);
                o.z = fmaxf(oB.x + bov.z, 0.f);
                o.w = fmaxf(oB.y + bov.w, 0.f);
                *(float4*)(out_team + (size_t)row * HIDDEN + H * H2 + colBase) = o;
            }
        }
        __syncthreads();
    }
}

// ---------------------------------------------------------------------------
extern "C" void kernel_launch(void* const* d_in, const int* in_sizes, int n_in,
                              void* d_out, int out_size) {
    const float* agent_h  = (const float*)d_in[0];
    const void*  team_idx = d_in[1];   // int32 or int64 -> detected on device
    // d_in[2] = n_teams scalar (derived from sizes instead)
    const float* W1 = (const float*)d_in[3];
    const float* b1 = (const float*)d_in[4];
    const float* W2 = (const float*)d_in[5];
    const float* b2 = (const float*)d_in[6];
    const float* Wo = (const float*)d_in[7];
    const float* bo = (const float*)d_in[8];

    const int n_agents = in_sizes[0] / HIDDEN;
    const int n_teams  = (out_size - n_agents) / HIDDEN;

    float* out_team = (float*)d_out;
    float* out_attn = out_team + (size_t)n_teams * HIDDEN;

    const int SMEM_BYTES = (HIDDEN * H2 + 64 * HIDDEN) * sizeof(float); // 196608
    cudaFuncSetAttribute(k_scores, cudaFuncAttributeMaxDynamicSharedMemorySize,
                         SMEM_BYTES);
    cudaFuncSetAttribute(k_out, cudaFuncAttributeMaxDynamicSharedMemorySize,
                         SMEM_BYTES);

    // dtype detect + CSR build
    k_detect<<<1, 256>>>(team_idx, n_agents, n_teams);
    k_zero_counts<<<(n_teams + 255) / 256, 256>>>(n_teams);
    k_count<<<(n_agents + 255) / 256, 256>>>(team_idx, n_agents, n_teams);
    k_scan<<<1, 1024>>>(n_teams);
    k_fill<<<(n_agents + 255) / 256, 256>>>(team_idx, n_agents, n_teams);

    // per-agent scores
    k_scores<<<148, 256, SMEM_BYTES>>>(agent_h, W1, b1, W2, b2, n_agents);

    // segment softmax + weighted pooling (also writes attn output)
    k_team<<<(n_teams + 7) / 8, 256>>>(agent_h, out_attn, n_teams);

    // output projection + relu
    dim3 og(74, 2, 1);
    k_out<<<og, 256, SMEM_BYTES>>>(Wo, bo, out_team, n_teams);
}